// round 13
// baseline (speedup 1.0000x reference)
#include <cuda_runtime.h>

typedef unsigned long long u64;
#define NFFT 1024
#define TWO_PI 6.2831853071795864769f

// ---- packed f32x2 helpers (sm_103a) ----
__device__ __forceinline__ u64 pk(float x, float y) {
    u64 u; asm("mov.b64 %0,{%1,%2};" : "=l"(u) : "f"(x), "f"(y)); return u;
}
__device__ __forceinline__ void upk(u64 u, float& x, float& y) {
    asm("mov.b64 {%0,%1},%2;" : "=f"(x), "=f"(y) : "l"(u));
}
__device__ __forceinline__ u64 padd(u64 a, u64 b) {
    u64 d; asm("add.rn.f32x2 %0,%1,%2;" : "=l"(d) : "l"(a), "l"(b)); return d;
}
__device__ __forceinline__ u64 pmul(u64 a, u64 b) {
    u64 d; asm("mul.rn.f32x2 %0,%1,%2;" : "=l"(d) : "l"(a), "l"(b)); return d;
}
__device__ __forceinline__ u64 pfma(u64 a, u64 b, u64 c) {
    u64 d; asm("fma.rn.f32x2 %0,%1,%2,%3;" : "=l"(d) : "l"(a), "l"(b), "l"(c)); return d;
}
__device__ __forceinline__ u64 psub(u64 a, u64 b) {  // a - b
    const u64 NEG1 = 0xBF800000BF800000ULL;
    return pfma(b, NEG1, a);
}
__device__ __forceinline__ u64 cmulc(u64 a, float br, float bi) {
    float ar, ai; upk(a, ar, ai);
    return pk(fmaf(-ai, bi, ar * br), fmaf(ar, bi, ai * br));
}
__device__ __forceinline__ u64 muli(u64 a) {  // a * i
    float ar, ai; upk(a, ar, ai);
    return pk(-ai, ar);
}

// Inverse (sign = +i) radix-4 butterfly on packed complex values.
__device__ __forceinline__ void bfly4_inv(u64 v[4]) {
    u64 t0 = padd(v[0], v[2]);
    u64 t1 = psub(v[0], v[2]);
    u64 t2 = padd(v[1], v[3]);
    u64 t3 = psub(v[1], v[3]);
    v[0] = padd(t0, t2);
    v[2] = psub(t0, t2);
    u64 w = muli(t3);
    v[1] = padd(t1, w);
    v[3] = psub(t1, w);
}

// In-register inverse 16-point DFT, natural order in and out.
__device__ __forceinline__ void dft16_inv(u64 v[16]) {
    const float C  = 0.70710678118654752f;   // cos(pi/4)
    const float C1 = 0.92387953251128676f;   // cos(pi/8)
    const float S1 = 0.38268343236508977f;   // sin(pi/8)
    u64 a[16];  // a[k1*4 + n2]
#pragma unroll
    for (int n2 = 0; n2 < 4; ++n2) {
        u64 t[4] = { v[n2], v[n2 + 4], v[n2 + 8], v[n2 + 12] };
        bfly4_inv(t);
        a[0 + n2] = t[0]; a[4 + n2] = t[1]; a[8 + n2] = t[2]; a[12 + n2] = t[3];
    }
    a[4 + 1]  = cmulc(a[4 + 1],  C1,  S1);
    a[4 + 2]  = cmulc(a[4 + 2],  C,   C);
    a[4 + 3]  = cmulc(a[4 + 3],  S1,  C1);
    a[8 + 1]  = cmulc(a[8 + 1],  C,   C);
    a[8 + 2]  = muli (a[8 + 2]);
    a[8 + 3]  = cmulc(a[8 + 3], -C,   C);
    a[12 + 1] = cmulc(a[12 + 1],  S1,  C1);
    a[12 + 2] = cmulc(a[12 + 2], -C,   C);
    a[12 + 3] = cmulc(a[12 + 3], -C1, -S1);
#pragma unroll
    for (int k1 = 0; k1 < 4; ++k1) {
        u64 t[4] = { a[k1 * 4 + 0], a[k1 * 4 + 1], a[k1 * 4 + 2], a[k1 * 4 + 3] };
        bfly4_inv(t);
        v[k1] = t[0]; v[k1 + 4] = t[1]; v[k1 + 8] = t[2]; v[k1 + 12] = t[3];
    }
}

// v[k] *= g * W^k, k=1..15, W=(c1,s1); gain g folded into the seeds
// (rotation steps by the UNSCALED (c1,s1) preserve the gain).
// Dual-seeded from W^1 and W^8 to halve the serial dependency depth.
__device__ __forceinline__ void twiddle_chain_dual(u64 v[16],
                                                   float c1, float s1,
                                                   float c8, float s8,
                                                   float g) {
    float cs = g * c1, sn = g * s1;
    v[1] = cmulc(v[1], cs, sn);
#pragma unroll
    for (int k = 2; k < 8; ++k) {
        float cn = fmaf(-sn, s1, cs * c1);
        float sx = fmaf( cs, s1, sn * c1);
        cs = cn; sn = sx;
        v[k] = cmulc(v[k], cs, sn);
    }
    cs = g * c8; sn = g * s8;
    v[8] = cmulc(v[8], cs, sn);
#pragma unroll
    for (int k = 9; k < 16; ++k) {
        float cn = fmaf(-sn, s1, cs * c1);
        float sx = fmaf( cs, s1, sn * c1);
        cs = cn; sn = sx;
        v[k] = cmulc(v[k], cs, sn);
    }
}

// 1024-pt inverse FFT, one row per 64-thread CTA. Twiddles by dual-seeded
// incremental rotation; 1/1024 folded into Phase B. Pairwise Phase C
// (LDS.128 in, STG.64 out). This round: evict-first (.cs) OUTPUT stores only
// (zero-reuse stream; early L2 writeback), loads left default.
__global__ void __launch_bounds__(64, 16)
ifft1024_kernel(const float* __restrict__ gre, const float* __restrict__ gim,
                float* __restrict__ outr, float* __restrict__ outi)
{
    __shared__ u64 s[NFFT];
    const int t = threadIdx.x;               // 0..63
    const size_t base = (size_t)blockIdx.x * NFFT;

    u64 v[16];

    // ---- Phase A: DFT16 over n1 (stride 64), twiddle W1024^(t*k1) ----
#pragma unroll
    for (int n1 = 0; n1 < 16; ++n1)
        v[n1] = pk(gre[base + 64 * n1 + t], gim[base + 64 * n1 + t]);
    dft16_inv(v);
    {
        const float th = (TWO_PI / 1024.0f) * (float)t;
        float s1, c1, s8, c8;
        __sincosf(th, &s1, &c1);
        __sincosf(8.0f * th, &s8, &c8);
        twiddle_chain_dual(v, c1, s1, c8, s8, 1.0f);
        const int hi = (t >> 4) << 8;
        const int lo = t & 15;
#pragma unroll
        for (int k1 = 0; k1 < 16; ++k1)
            s[hi | (k1 << 4) | (lo ^ ((k1 & 3) << 2))] = v[k1];
    }
    __syncthreads();

    // ---- Phase B: DFT16 over m (n2 = 4m+q), twiddle SC * W64^(q*c) ----
    {
        const int k1 = t >> 2, q = t & 3;
#pragma unroll
        for (int m = 0; m < 16; ++m) {
            const int n2 = 4 * m + q;
            const int phys = ((n2 >> 4) << 8) | (k1 << 4) | ((n2 & 15) ^ ((k1 & 3) << 2));
            v[m] = s[phys];
        }
        dft16_inv(v);
        {
            const float SCALE = 1.0f / 1024.0f;   // exact power of 2
            const float ph = (TWO_PI / 64.0f) * (float)q;
            float s1, c1, s8, c8;
            __sincosf(ph, &s1, &c1);
            __sincosf(8.0f * ph, &s8, &c8);
            const u64 SCpk = 0x3A8000003A800000ULL;  // packed (1/1024, 1/1024)
            v[0] = pmul(v[0], SCpk);
            twiddle_chain_dual(v, c1, s1, c8, s8, SCALE);
        }
        __syncthreads();   // all reads of exchange-1 complete before reuse
#pragma unroll
        for (int c = 0; c < 16; ++c) {
            const int idx = k1 + 16 * c + 256 * q;
            s[idx ^ (q << 2)] = v[c];
        }
    }
    __syncthreads();

    // ---- Phase C: final radix-4 across q, pairwise columns p = 2t(+128) ----
    {
#pragma unroll
        for (int jj = 0; jj < 2; ++jj) {
            const int p = 2 * t + 128 * jj;   // even: pair (p, p+1)
            u64 lo[4], hi[4];
#pragma unroll
            for (int q = 0; q < 4; ++q) {
                const int idx = (p + 256 * q) ^ (q << 2);   // even -> 16B aligned
                ulonglong2 vec = *reinterpret_cast<const ulonglong2*>(&s[idx]);
                lo[q] = vec.x;   // column p
                hi[q] = vec.y;   // column p+1
            }
            bfly4_inv(lo);
            bfly4_inv(hi);
#pragma unroll
            for (int d = 0; d < 4; ++d) {
                float ar, ai, br, bi;
                upk(lo[d], ar, ai);
                upk(hi[d], br, bi);
                __stcs(reinterpret_cast<float2*>(&outr[base + p + 256 * d]),
                       make_float2(ar, br));
                __stcs(reinterpret_cast<float2*>(&outi[base + p + 256 * d]),
                       make_float2(ai, bi));
            }
        }
    }
}

extern "C" void kernel_launch(void* const* d_in, const int* in_sizes, int n_in,
                              void* d_out, int out_size) {
    const float* re = (const float*)d_in[0];
    const float* im = (const float*)d_in[1];
    float* out = (float*)d_out;
    const int half = out_size / 2;           // y_real then y_imag, concatenated
    const int nrows = in_sizes[0] / NFFT;    // 32768
    ifft1024_kernel<<<nrows, 64>>>(re, im, out, out + half);
}

// round 14
// speedup vs baseline: 1.0055x; 1.0055x over previous
#include <cuda_runtime.h>

typedef unsigned long long u64;
#define NFFT 1024
#define TWO_PI 6.2831853071795864769f

// ---- packed f32x2 helpers (sm_103a) ----
__device__ __forceinline__ u64 pk(float x, float y) {
    u64 u; asm("mov.b64 %0,{%1,%2};" : "=l"(u) : "f"(x), "f"(y)); return u;
}
__device__ __forceinline__ void upk(u64 u, float& x, float& y) {
    asm("mov.b64 {%0,%1},%2;" : "=f"(x), "=f"(y) : "l"(u));
}
__device__ __forceinline__ u64 padd(u64 a, u64 b) {
    u64 d; asm("add.rn.f32x2 %0,%1,%2;" : "=l"(d) : "l"(a), "l"(b)); return d;
}
__device__ __forceinline__ u64 pmul(u64 a, u64 b) {
    u64 d; asm("mul.rn.f32x2 %0,%1,%2;" : "=l"(d) : "l"(a), "l"(b)); return d;
}
__device__ __forceinline__ u64 pfma(u64 a, u64 b, u64 c) {
    u64 d; asm("fma.rn.f32x2 %0,%1,%2,%3;" : "=l"(d) : "l"(a), "l"(b), "l"(c)); return d;
}
__device__ __forceinline__ u64 psub(u64 a, u64 b) {  // a - b
    const u64 NEG1 = 0xBF800000BF800000ULL;
    return pfma(b, NEG1, a);
}
__device__ __forceinline__ u64 cmulc(u64 a, float br, float bi) {
    float ar, ai; upk(a, ar, ai);
    return pk(fmaf(-ai, bi, ar * br), fmaf(ar, bi, ai * br));
}
__device__ __forceinline__ u64 muli(u64 a) {  // a * i
    float ar, ai; upk(a, ar, ai);
    return pk(-ai, ar);
}

// Inverse (sign = +i) radix-4 butterfly on packed complex values.
__device__ __forceinline__ void bfly4_inv(u64 v[4]) {
    u64 t0 = padd(v[0], v[2]);
    u64 t1 = psub(v[0], v[2]);
    u64 t2 = padd(v[1], v[3]);
    u64 t3 = psub(v[1], v[3]);
    v[0] = padd(t0, t2);
    v[2] = psub(t0, t2);
    u64 w = muli(t3);
    v[1] = padd(t1, w);
    v[3] = psub(t1, w);
}

// In-register inverse 16-point DFT, natural order in and out.
__device__ __forceinline__ void dft16_inv(u64 v[16]) {
    const float C  = 0.70710678118654752f;   // cos(pi/4)
    const float C1 = 0.92387953251128676f;   // cos(pi/8)
    const float S1 = 0.38268343236508977f;   // sin(pi/8)
    u64 a[16];  // a[k1*4 + n2]
#pragma unroll
    for (int n2 = 0; n2 < 4; ++n2) {
        u64 t[4] = { v[n2], v[n2 + 4], v[n2 + 8], v[n2 + 12] };
        bfly4_inv(t);
        a[0 + n2] = t[0]; a[4 + n2] = t[1]; a[8 + n2] = t[2]; a[12 + n2] = t[3];
    }
    a[4 + 1]  = cmulc(a[4 + 1],  C1,  S1);
    a[4 + 2]  = cmulc(a[4 + 2],  C,   C);
    a[4 + 3]  = cmulc(a[4 + 3],  S1,  C1);
    a[8 + 1]  = cmulc(a[8 + 1],  C,   C);
    a[8 + 2]  = muli (a[8 + 2]);
    a[8 + 3]  = cmulc(a[8 + 3], -C,   C);
    a[12 + 1] = cmulc(a[12 + 1],  S1,  C1);
    a[12 + 2] = cmulc(a[12 + 2], -C,   C);
    a[12 + 3] = cmulc(a[12 + 3], -C1, -S1);
#pragma unroll
    for (int k1 = 0; k1 < 4; ++k1) {
        u64 t[4] = { a[k1 * 4 + 0], a[k1 * 4 + 1], a[k1 * 4 + 2], a[k1 * 4 + 3] };
        bfly4_inv(t);
        v[k1] = t[0]; v[k1 + 4] = t[1]; v[k1 + 8] = t[2]; v[k1 + 12] = t[3];
    }
}

// v[k] *= g * W^k, k=1..15, W=(c1,s1); gain g folded into the seeds
// (rotation steps by the UNSCALED (c1,s1) preserve the gain).
// Dual-seeded from W^1 and W^8 to halve the serial dependency depth.
__device__ __forceinline__ void twiddle_chain_dual(u64 v[16],
                                                   float c1, float s1,
                                                   float c8, float s8,
                                                   float g) {
    float cs = g * c1, sn = g * s1;
    v[1] = cmulc(v[1], cs, sn);
#pragma unroll
    for (int k = 2; k < 8; ++k) {
        float cn = fmaf(-sn, s1, cs * c1);
        float sx = fmaf( cs, s1, sn * c1);
        cs = cn; sn = sx;
        v[k] = cmulc(v[k], cs, sn);
    }
    cs = g * c8; sn = g * s8;
    v[8] = cmulc(v[8], cs, sn);
#pragma unroll
    for (int k = 9; k < 16; ++k) {
        float cn = fmaf(-sn, s1, cs * c1);
        float sx = fmaf( cs, s1, sn * c1);
        cs = cn; sn = sx;
        v[k] = cmulc(v[k], cs, sn);
    }
}

// 1024-pt inverse FFT, one row per 64-thread CTA (final, memory-wall-bound):
// N = 16*64 Cooley-Tukey, two conflict-free shared exchanges, dual-seeded
// incremental twiddles, 1/1024 folded into Phase B, pairwise Phase C
// (LDS.128 in, STG.64 out). Measured: 81.95 us wall / 75.9 us ncu,
// 6.34 TB/s (~80% DRAM), rel_err 1.1e-6.
__global__ void __launch_bounds__(64, 16)
ifft1024_kernel(const float* __restrict__ gre, const float* __restrict__ gim,
                float* __restrict__ outr, float* __restrict__ outi)
{
    __shared__ u64 s[NFFT];
    const int t = threadIdx.x;               // 0..63
    const size_t base = (size_t)blockIdx.x * NFFT;

    u64 v[16];

    // ---- Phase A: DFT16 over n1 (stride 64), twiddle W1024^(t*k1) ----
#pragma unroll
    for (int n1 = 0; n1 < 16; ++n1)
        v[n1] = pk(gre[base + 64 * n1 + t], gim[base + 64 * n1 + t]);
    dft16_inv(v);
    {
        const float th = (TWO_PI / 1024.0f) * (float)t;
        float s1, c1, s8, c8;
        __sincosf(th, &s1, &c1);
        __sincosf(8.0f * th, &s8, &c8);
        twiddle_chain_dual(v, c1, s1, c8, s8, 1.0f);
        const int hi = (t >> 4) << 8;
        const int lo = t & 15;
#pragma unroll
        for (int k1 = 0; k1 < 16; ++k1)
            s[hi | (k1 << 4) | (lo ^ ((k1 & 3) << 2))] = v[k1];
    }
    __syncthreads();

    // ---- Phase B: DFT16 over m (n2 = 4m+q), twiddle SC * W64^(q*c) ----
    {
        const int k1 = t >> 2, q = t & 3;
#pragma unroll
        for (int m = 0; m < 16; ++m) {
            const int n2 = 4 * m + q;
            const int phys = ((n2 >> 4) << 8) | (k1 << 4) | ((n2 & 15) ^ ((k1 & 3) << 2));
            v[m] = s[phys];
        }
        dft16_inv(v);
        {
            const float SCALE = 1.0f / 1024.0f;   // exact power of 2
            const float ph = (TWO_PI / 64.0f) * (float)q;
            float s1, c1, s8, c8;
            __sincosf(ph, &s1, &c1);
            __sincosf(8.0f * ph, &s8, &c8);
            const u64 SCpk = 0x3A8000003A800000ULL;  // packed (1/1024, 1/1024)
            v[0] = pmul(v[0], SCpk);
            twiddle_chain_dual(v, c1, s1, c8, s8, SCALE);
        }
        __syncthreads();   // all reads of exchange-1 complete before reuse
#pragma unroll
        for (int c = 0; c < 16; ++c) {
            const int idx = k1 + 16 * c + 256 * q;
            s[idx ^ (q << 2)] = v[c];
        }
    }
    __syncthreads();

    // ---- Phase C: final radix-4 across q, pairwise columns p = 2t(+128) ----
    {
#pragma unroll
        for (int jj = 0; jj < 2; ++jj) {
            const int p = 2 * t + 128 * jj;   // even: pair (p, p+1)
            u64 lo[4], hi[4];
#pragma unroll
            for (int q = 0; q < 4; ++q) {
                const int idx = (p + 256 * q) ^ (q << 2);   // even -> 16B aligned
                ulonglong2 vec = *reinterpret_cast<const ulonglong2*>(&s[idx]);
                lo[q] = vec.x;   // column p
                hi[q] = vec.y;   // column p+1
            }
            bfly4_inv(lo);
            bfly4_inv(hi);
#pragma unroll
            for (int d = 0; d < 4; ++d) {
                float ar, ai, br, bi;
                upk(lo[d], ar, ai);
                upk(hi[d], br, bi);
                *reinterpret_cast<float2*>(&outr[base + p + 256 * d]) = make_float2(ar, br);
                *reinterpret_cast<float2*>(&outi[base + p + 256 * d]) = make_float2(ai, bi);
            }
        }
    }
}

extern "C" void kernel_launch(void* const* d_in, const int* in_sizes, int n_in,
                              void* d_out, int out_size) {
    const float* re = (const float*)d_in[0];
    const float* im = (const float*)d_in[1];
    float* out = (float*)d_out;
    const int half = out_size / 2;           // y_real then y_imag, concatenated
    const int nrows = in_sizes[0] / NFFT;    // 32768
    ifft1024_kernel<<<nrows, 64>>>(re, im, out, out + half);
}